// round 1
// baseline (speedup 1.0000x reference)
#include <cuda_runtime.h>
#include <math.h>

// ---------------------------------------------------------------------------
// Problem constants
//   x:      (8, 32, 32, 512)  -> rows = 8192, c = 512
//   w_qkv:  (512, 1536)   q/k/v interleaved per head: j = h*192 + part*64 + d
//   attention: b=8, heads=8, n=1024, dh=64, scale = 8^-0.5
//   w_out:  (512, 512), b_out: (512,)
// ---------------------------------------------------------------------------

// Scratch (static device globals; allocation inside kernel_launch is forbidden)
__device__ float g_Q[8 * 8 * 64 * 1024];   // [b][h][d][n]  (transposed for attn)
__device__ float g_K[8 * 8 * 64 * 1024];   // [b][h][d][n]
__device__ float g_V[8 * 8 * 1024 * 64];   // [b][h][n][d]
__device__ float g_O[8192 * 512];          // [b*n][h*64+d]

// FMA-only exp (MUFU on sm_103a is ~0.5 op/cyc/SM; 67M exps would dominate).
// exp(x) = 2^(x*log2e); range reduce, deg-5 Taylor in t = f*ln2, |t| <= 0.347.
__device__ __forceinline__ float fast_exp(float x) {
    float y = x * 1.4426950408889634f;
    y = fmaxf(y, -126.0f);
    y = fminf(y, 126.0f);
    float nf = rintf(y);
    float f = y - nf;                 // [-0.5, 0.5]
    float t = f * 0.6931471805599453f;
    float p = 8.3333337e-3f;          // 1/120
    p = fmaf(p, t, 4.1666668e-2f);    // 1/24
    p = fmaf(p, t, 0.16666667f);
    p = fmaf(p, t, 0.5f);
    p = fmaf(p, t, 1.0f);
    p = fmaf(p, t, 1.0f);
    int ni = (int)nf;
    return p * __int_as_float((ni + 127) << 23);
}

// ---------------------------------------------------------------------------
// Kernel 1: QKV projection.  C(8192,1536) = x(8192,512) @ w_qkv(512,1536)
// 128x128 block tile, BK=8, 256 threads, 8x8 per-thread microtile.
// Epilogue scatters into g_Q/g_K/g_V layouts.
// ---------------------------------------------------------------------------
__global__ __launch_bounds__(256) void qkv_gemm(const float* __restrict__ A,
                                                const float* __restrict__ B) {
    __shared__ float As[8][132];   // transposed A tile, padded (conflict-free)
    __shared__ float Bs[8][128];

    const int tid = threadIdx.x;
    const int ty = tid >> 4, tx = tid & 15;
    const int row0 = blockIdx.y * 128;
    const int col0 = blockIdx.x * 128;

    float acc[8][8];
#pragma unroll
    for (int i = 0; i < 8; i++)
#pragma unroll
        for (int j = 0; j < 8; j++) acc[i][j] = 0.0f;

    const int ar = tid >> 1, ac = (tid & 1) << 2;      // A: 128 rows x 8 cols
    const int br = tid >> 5, bc = (tid & 31) << 2;     // B: 8 rows x 128 cols
    const float* Aptr = A + (size_t)(row0 + ar) * 512 + ac;
    const float* Bptr = B + (size_t)br * 1536 + col0 + bc;

    for (int k0 = 0; k0 < 512; k0 += 8) {
        float4 av = *(const float4*)(Aptr + k0);
        float4 bv = *(const float4*)(Bptr + (size_t)k0 * 1536);
        __syncthreads();
        As[ac + 0][ar] = av.x; As[ac + 1][ar] = av.y;
        As[ac + 2][ar] = av.z; As[ac + 3][ar] = av.w;
        *(float4*)&Bs[br][bc] = bv;
        __syncthreads();
#pragma unroll
        for (int kk = 0; kk < 8; kk++) {
            float4 a0 = *(float4*)&As[kk][ty * 8];
            float4 a1 = *(float4*)&As[kk][ty * 8 + 4];
            float4 b0 = *(float4*)&Bs[kk][tx * 8];
            float4 b1 = *(float4*)&Bs[kk][tx * 8 + 4];
            float a[8] = {a0.x, a0.y, a0.z, a0.w, a1.x, a1.y, a1.z, a1.w};
            float b[8] = {b0.x, b0.y, b0.z, b0.w, b1.x, b1.y, b1.z, b1.w};
#pragma unroll
            for (int i = 0; i < 8; i++)
#pragma unroll
                for (int j = 0; j < 8; j++)
                    acc[i][j] = fmaf(a[i], b[j], acc[i][j]);
        }
    }

    // Scatter epilogue. j group of 8 never crosses a part/head boundary (8|64).
    const int j0 = col0 + tx * 8;
    const int h = j0 / 192;
    const int part = (j0 % 192) >> 6;
    const int d0 = j0 & 63;
    const int rowg0 = row0 + ty * 8;          // 8 rows stay within one b (8|1024)
    const int b_idx = rowg0 >> 10;
    const int n0 = rowg0 & 1023;
    const int bh = b_idx * 8 + h;

    if (part < 2) {
        float* dst = (part == 0 ? g_Q : g_K) + (size_t)bh * 64 * 1024;
#pragma unroll
        for (int c = 0; c < 8; c++) {
            int d = d0 + c;
            *(float4*)&dst[(size_t)d * 1024 + n0] =
                make_float4(acc[0][c], acc[1][c], acc[2][c], acc[3][c]);
            *(float4*)&dst[(size_t)d * 1024 + n0 + 4] =
                make_float4(acc[4][c], acc[5][c], acc[6][c], acc[7][c]);
        }
    } else {
        float* dst = g_V + ((size_t)bh * 1024) * 64 + d0;
#pragma unroll
        for (int r = 0; r < 8; r++) {
            *(float4*)&dst[(size_t)(n0 + r) * 64] =
                make_float4(acc[r][0], acc[r][1], acc[r][2], acc[r][3]);
            *(float4*)&dst[(size_t)(n0 + r) * 64 + 4] =
                make_float4(acc[r][4], acc[r][5], acc[r][6], acc[r][7]);
        }
    }
}

// ---------------------------------------------------------------------------
// Kernel 2: fused flash attention per (b,h).
// Block: 256 threads (16x16), BM=128 q-rows, j streamed in tiles of 128.
// smem: Qs[64][128] Ks[64][128] Vs[128][68] Ps[128][132] = ~164 KB dynamic.
// ---------------------------------------------------------------------------
__global__ __launch_bounds__(256) void attn_kernel() {
    extern __shared__ float sm[];
    float* Qs = sm;                    // [d][i]  64 x 128
    float* Ks = Qs + 64 * 128;         // [d][j]  64 x 128
    float* Vs = Ks + 64 * 128;         // [j][d]  128 x 68 (padded)
    float* Ps = Vs + 128 * 68;         // [i][j]  128 x 132 (padded)

    const int tid = threadIdx.x;
    const int ty = tid >> 4, tx = tid & 15;
    const int bh = blockIdx.y;
    const int i0blk = blockIdx.x * 128;
    const float* Qt = g_Q + (size_t)bh * 64 * 1024;
    const float* Kt = g_K + (size_t)bh * 64 * 1024;
    const float* Vt = g_V + (size_t)bh * 1024 * 64;
    const int iloc = ty * 8, jloc = tx * 8;
    const float scale = 0.35355339059327373f;   // 8^-0.5 (batch size!)

    // Load Q tile (128 rows x 64 d), already transposed in gmem.
#pragma unroll
    for (int c = 0; c < 8; c++) {
        int f4 = c * 256 + tid;
        int d = f4 >> 5, i4 = (f4 & 31) << 2;
        *(float4*)&Qs[d * 128 + i4] = *(const float4*)&Qt[(size_t)d * 1024 + i0blk + i4];
    }

    float Oa[8][4];
    float mrow[8], lrow[8];
#pragma unroll
    for (int r = 0; r < 8; r++) {
        mrow[r] = -1e30f; lrow[r] = 0.0f;
#pragma unroll
        for (int c = 0; c < 4; c++) Oa[r][c] = 0.0f;
    }

    for (int jt = 0; jt < 8; jt++) {
        const int j0 = jt * 128;
        // Load K tile
#pragma unroll
        for (int c = 0; c < 8; c++) {
            int f4 = c * 256 + tid;
            int d = f4 >> 5, j4 = (f4 & 31) << 2;
            *(float4*)&Ks[d * 128 + j4] = *(const float4*)&Kt[(size_t)d * 1024 + j0 + j4];
        }
        __syncthreads();

        // S tile: 8x8 per thread over d=64
        float S[8][8];
#pragma unroll
        for (int i = 0; i < 8; i++)
#pragma unroll
            for (int j = 0; j < 8; j++) S[i][j] = 0.0f;

#pragma unroll 8
        for (int d = 0; d < 64; d++) {
            float4 qa = *(float4*)&Qs[d * 128 + iloc];
            float4 qb = *(float4*)&Qs[d * 128 + iloc + 4];
            float4 ka = *(float4*)&Ks[d * 128 + jloc];
            float4 kb = *(float4*)&Ks[d * 128 + jloc + 4];
            float a[8] = {qa.x, qa.y, qa.z, qa.w, qb.x, qb.y, qb.z, qb.w};
            float b[8] = {ka.x, ka.y, ka.z, ka.w, kb.x, kb.y, kb.z, kb.w};
#pragma unroll
            for (int i = 0; i < 8; i++)
#pragma unroll
                for (int j = 0; j < 8; j++)
                    S[i][j] = fmaf(a[i], b[j], S[i][j]);
        }

        // Online softmax update. Row r is owned by the 16 lanes sharing ty
        // (contiguous 16-lane segment of the warp -> shfl width 16).
#pragma unroll
        for (int r = 0; r < 8; r++) {
            float rmax = -1e30f;
#pragma unroll
            for (int c = 0; c < 8; c++) { S[r][c] *= scale; rmax = fmaxf(rmax, S[r][c]); }
#pragma unroll
            for (int off = 8; off > 0; off >>= 1)
                rmax = fmaxf(rmax, __shfl_xor_sync(0xffffffffu, rmax, off, 16));
            float mnew = fmaxf(mrow[r], rmax);
            float corr = fast_exp(mrow[r] - mnew);
            float rsum = 0.0f;
#pragma unroll
            for (int c = 0; c < 8; c++) {
                float pv = fast_exp(S[r][c] - mnew);
                S[r][c] = pv;
                rsum += pv;
            }
#pragma unroll
            for (int off = 8; off > 0; off >>= 1)
                rsum += __shfl_xor_sync(0xffffffffu, rsum, off, 16);
            lrow[r] = lrow[r] * corr + rsum;
            mrow[r] = mnew;
#pragma unroll
            for (int c = 0; c < 4; c++) Oa[r][c] *= corr;
        }

        // Write P (natural [i][j], vectorized along j -> conflict-free STS.128)
#pragma unroll
        for (int r = 0; r < 8; r++) {
            *(float4*)&Ps[(iloc + r) * 132 + jloc] =
                make_float4(S[r][0], S[r][1], S[r][2], S[r][3]);
            *(float4*)&Ps[(iloc + r) * 132 + jloc + 4] =
                make_float4(S[r][4], S[r][5], S[r][6], S[r][7]);
        }
        // Load V tile (independent buffer; covered by the same barrier)
#pragma unroll
        for (int c = 0; c < 8; c++) {
            int f4 = c * 256 + tid;
            int j = f4 >> 4, dq = (f4 & 15) << 2;
            *(float4*)&Vs[j * 68 + dq] = *(const float4*)&Vt[(size_t)(j0 + j) * 64 + dq];
        }
        __syncthreads();

        // O += P @ V   (thread: 8 rows x 4 d-cols)
#pragma unroll 4
        for (int j = 0; j < 128; j++) {
            float4 bv = *(float4*)&Vs[j * 68 + tx * 4];
            float av[8];
#pragma unroll
            for (int r = 0; r < 8; r++) av[r] = Ps[(iloc + r) * 132 + j];
#pragma unroll
            for (int r = 0; r < 8; r++) {
                Oa[r][0] = fmaf(av[r], bv.x, Oa[r][0]);
                Oa[r][1] = fmaf(av[r], bv.y, Oa[r][1]);
                Oa[r][2] = fmaf(av[r], bv.z, Oa[r][2]);
                Oa[r][3] = fmaf(av[r], bv.w, Oa[r][3]);
            }
        }
        __syncthreads();
    }

    // Epilogue: normalize, write to g_O[(b*1024+i)][h*64+d]
    const int b_idx = bh >> 3, h = bh & 7;
#pragma unroll
    for (int r = 0; r < 8; r++) {
        float inv = 1.0f / lrow[r];
        size_t rowg = (size_t)b_idx * 1024 + i0blk + iloc + r;
        *(float4*)&g_O[rowg * 512 + h * 64 + tx * 4] =
            make_float4(Oa[r][0] * inv, Oa[r][1] * inv, Oa[r][2] * inv, Oa[r][3] * inv);
    }
}

// ---------------------------------------------------------------------------
// Kernel 3: output projection.  out(8192,512) = g_O @ w_out + b_out
// ---------------------------------------------------------------------------
__global__ __launch_bounds__(256) void out_gemm(const float* __restrict__ B,
                                                const float* __restrict__ bias,
                                                float* __restrict__ C) {
    __shared__ float As[8][132];
    __shared__ float Bs[8][128];

    const int tid = threadIdx.x;
    const int ty = tid >> 4, tx = tid & 15;
    const int row0 = blockIdx.y * 128;
    const int col0 = blockIdx.x * 128;

    float acc[8][8];
#pragma unroll
    for (int i = 0; i < 8; i++)
#pragma unroll
        for (int j = 0; j < 8; j++) acc[i][j] = 0.0f;

    const int ar = tid >> 1, ac = (tid & 1) << 2;
    const int br = tid >> 5, bc = (tid & 31) << 2;
    const float* Aptr = g_O + (size_t)(row0 + ar) * 512 + ac;
    const float* Bptr = B + (size_t)br * 512 + col0 + bc;

    for (int k0 = 0; k0 < 512; k0 += 8) {
        float4 av = *(const float4*)(Aptr + k0);
        float4 bv = *(const float4*)(Bptr + (size_t)k0 * 512);
        __syncthreads();
        As[ac + 0][ar] = av.x; As[ac + 1][ar] = av.y;
        As[ac + 2][ar] = av.z; As[ac + 3][ar] = av.w;
        *(float4*)&Bs[br][bc] = bv;
        __syncthreads();
#pragma unroll
        for (int kk = 0; kk < 8; kk++) {
            float4 a0 = *(float4*)&As[kk][ty * 8];
            float4 a1 = *(float4*)&As[kk][ty * 8 + 4];
            float4 b0 = *(float4*)&Bs[kk][tx * 8];
            float4 b1 = *(float4*)&Bs[kk][tx * 8 + 4];
            float a[8] = {a0.x, a0.y, a0.z, a0.w, a1.x, a1.y, a1.z, a1.w};
            float b[8] = {b0.x, b0.y, b0.z, b0.w, b1.x, b1.y, b1.z, b1.w};
#pragma unroll
            for (int i = 0; i < 8; i++)
#pragma unroll
                for (int j = 0; j < 8; j++)
                    acc[i][j] = fmaf(a[i], b[j], acc[i][j]);
        }
    }

    float4 bi0 = *(const float4*)&bias[col0 + tx * 8];
    float4 bi1 = *(const float4*)&bias[col0 + tx * 8 + 4];
#pragma unroll
    for (int r = 0; r < 8; r++) {
        size_t rowg = (size_t)(row0 + ty * 8 + r);
        *(float4*)&C[rowg * 512 + col0 + tx * 8] =
            make_float4(acc[r][0] + bi0.x, acc[r][1] + bi0.y,
                        acc[r][2] + bi0.z, acc[r][3] + bi0.w);
        *(float4*)&C[rowg * 512 + col0 + tx * 8 + 4] =
            make_float4(acc[r][4] + bi1.x, acc[r][5] + bi1.y,
                        acc[r][6] + bi1.z, acc[r][7] + bi1.w);
    }
}

// ---------------------------------------------------------------------------
extern "C" void kernel_launch(void* const* d_in, const int* in_sizes, int n_in,
                              void* d_out, int out_size) {
    const float* x     = (const float*)d_in[0];
    const float* w_qkv = (const float*)d_in[1];
    const float* w_out = (const float*)d_in[2];
    const float* b_out = (const float*)d_in[3];
    float* out = (float*)d_out;

    const size_t attn_smem =
        (size_t)(64 * 128 + 64 * 128 + 128 * 68 + 128 * 132) * sizeof(float);
    cudaFuncSetAttribute(attn_kernel, cudaFuncAttributeMaxDynamicSharedMemorySize,
                         (int)attn_smem);

    qkv_gemm<<<dim3(12, 64), 256>>>(x, w_qkv);
    attn_kernel<<<dim3(8, 64), 256, attn_smem>>>();
    out_gemm<<<dim3(4, 64), 256>>>(w_out, b_out, out);
}